// round 12
// baseline (speedup 1.0000x reference)
#include <cuda_runtime.h>
#include <math.h>

#define BATCH 16
#define FH 192
#define FW 192
#define NA 9
#define NPI (FH*FW*NA)      /* 331776 anchors per image */
#define NPI4 (NPI/4)        /* 82944 */
#define PRE 6000
#define POST 1000
#define CAP 8192            /* candidate capacity per image (power of two for bitonic) */
#define HB 65536            /* histogram buckets = top 16 bits of fp32 score */
#define PREW 188            /* suppression-mask words per row (6016 bits) */

// ---------------- device scratch (no allocations allowed) ----------------
__device__ unsigned int       g_hist[BATCH * HB];        // 4 MB (zeroed by k_collect each pass)
__device__ unsigned int       g_cnt[BATCH];
__device__ int                g_thresh[BATCH];
__device__ unsigned long long g_keys[BATCH * CAP];       // 1 MB
__device__ float4             g_boxes[BATCH * PRE];      // 384 KB
__device__ unsigned int       g_mask[BATCH * PRE * PREW]; // 72 MB suppression matrix

// ---------------- kernel 1: score-bit histogram per image -----------------
// grid (81, BATCH) x 256: exactly 4 float4 per thread, batched for MLP.
__global__ void k_hist(const float* __restrict__ scores) {
    int b = blockIdx.y;
    const float4* s4 = (const float4*)(scores + (size_t)b * NPI);
    unsigned* h = g_hist + (size_t)b * HB;
    int i = blockIdx.x * blockDim.x + threadIdx.x;
    int step = gridDim.x * blockDim.x;                  // 20736 = NPI4/4
    float4 v0 = s4[i];
    float4 v1 = s4[i + step];
    float4 v2 = s4[i + 2 * step];
    float4 v3 = s4[i + 3 * step];
    atomicAdd(&h[__float_as_uint(v0.x) >> 16], 1u);
    atomicAdd(&h[__float_as_uint(v0.y) >> 16], 1u);
    atomicAdd(&h[__float_as_uint(v0.z) >> 16], 1u);
    atomicAdd(&h[__float_as_uint(v0.w) >> 16], 1u);
    atomicAdd(&h[__float_as_uint(v1.x) >> 16], 1u);
    atomicAdd(&h[__float_as_uint(v1.y) >> 16], 1u);
    atomicAdd(&h[__float_as_uint(v1.z) >> 16], 1u);
    atomicAdd(&h[__float_as_uint(v1.w) >> 16], 1u);
    atomicAdd(&h[__float_as_uint(v2.x) >> 16], 1u);
    atomicAdd(&h[__float_as_uint(v2.y) >> 16], 1u);
    atomicAdd(&h[__float_as_uint(v2.z) >> 16], 1u);
    atomicAdd(&h[__float_as_uint(v2.w) >> 16], 1u);
    atomicAdd(&h[__float_as_uint(v3.x) >> 16], 1u);
    atomicAdd(&h[__float_as_uint(v3.y) >> 16], 1u);
    atomicAdd(&h[__float_as_uint(v3.z) >> 16], 1u);
    atomicAdd(&h[__float_as_uint(v3.w) >> 16], 1u);
}

// ---------------- kernel 2: per-image threshold bucket --------------------
// Largest bucket T such that count(bucket >= T) >= PRE; resets g_cnt.
__global__ void k_thresh() {
    int b = blockIdx.x;
    int t = threadIdx.x;               // 256 threads, each sums a 256-bucket chunk
    __shared__ unsigned csum[256];
    __shared__ unsigned sbuf[256];
    __shared__ unsigned sfin[256];
    __shared__ int s_chunk;
    __shared__ unsigned s_above;
    const unsigned* h = g_hist + (size_t)b * HB;
    int base = t * 256;
    unsigned s = 0;
    for (int i = 0; i < 256; i++) s += h[base + i];
    csum[t] = s;
    __syncthreads();
    if (t == 0) {
        unsigned cum = 0;
        int c = 255;
        for (; c >= 0; c--) {
            if (cum + csum[c] >= PRE) break;
            cum += csum[c];
        }
        s_chunk = c;
        s_above = cum;                 // count strictly above chunk c
        g_cnt[b] = 0u;                 // reset candidate counter for k_collect
    }
    __syncthreads();
    int c = s_chunk;
    unsigned above = s_above;
    sbuf[t] = h[c * 256 + t];
    __syncthreads();
    // inclusive suffix sum (Hillis-Steele)
    for (int d = 1; d < 256; d <<= 1) {
        unsigned v = (t + d < 256) ? sbuf[t + d] : 0u;
        __syncthreads();
        sbuf[t] += v;
        __syncthreads();
    }
    sfin[t] = sbuf[t];
    __syncthreads();
    // largest index i with suffix(i)+above >= PRE (suffix is non-increasing)
    bool ok = (sfin[t] + above >= PRE);
    bool next_ok = (t < 255) ? (sfin[t + 1] + above >= PRE) : false;
    if (ok && !next_ok) g_thresh[b] = c * 256 + t;
}

// ---------------- kernel 3: collect candidate keys + zero histogram -------
// key = (score_bits << 32) | (~idx): descending sort => score desc, then idx asc
// (matches lax.top_k stable tie-breaking exactly).
__global__ void k_collect(const float* __restrict__ scores) {
    int b = blockIdx.y;
    const float4* s4 = (const float4*)(scores + (size_t)b * NPI);
    int T = g_thresh[b];
    int i = blockIdx.x * blockDim.x + threadIdx.x;
    int step = gridDim.x * blockDim.x;                  // 20736
    float4 v[4];
    v[0] = s4[i]; v[1] = s4[i + step]; v[2] = s4[i + 2 * step];
    v[3] = s4[i + 3 * step];
#pragma unroll
    for (int q = 0; q < 4; q++) {
        unsigned bw[4] = {__float_as_uint(v[q].x), __float_as_uint(v[q].y),
                          __float_as_uint(v[q].z), __float_as_uint(v[q].w)};
#pragma unroll
        for (int c = 0; c < 4; c++) {
            if ((int)(bw[c] >> 16) >= T) {
                unsigned pos = atomicAdd(&g_cnt[b], 1u);
                if (pos < CAP) {
                    unsigned idx = 4u * (unsigned)(i + q * step) + (unsigned)c;
                    g_keys[(size_t)b * CAP + pos] =
                        ((unsigned long long)bw[c] << 32) |
                        (unsigned long long)(0xFFFFFFFFu - idx);
                }
            }
        }
    }
    // zero histogram for next replay
    unsigned* h = g_hist + (size_t)b * HB;
    for (int j = i; j < HB; j += step) h[j] = 0u;
}

// ---------------- kernel 4: per-image bitonic sort + decode ---------------
__global__ __launch_bounds__(1024) void k_sort_decode(
        const float* __restrict__ deltas, const float* __restrict__ banch) {
    extern __shared__ unsigned long long sk[];   // CAP u64 = 64 KB
    __shared__ float sbase[NA * 4];
    int b = blockIdx.x, tid = threadIdx.x, bs = blockDim.x;

    unsigned cnt = g_cnt[b];
    if (cnt > CAP) cnt = CAP;
    for (int i = tid; i < CAP; i += bs)
        sk[i] = ((unsigned)i < cnt) ? g_keys[(size_t)b * CAP + i] : 0ull;
    if (tid < NA * 4) sbase[tid] = banch[tid];
    __syncthreads();

    // bitonic sort, descending
    for (int k = 2; k <= CAP; k <<= 1) {
        for (int j = k >> 1; j > 0; j >>= 1) {
            for (int i = tid; i < CAP; i += bs) {
                int ixj = i ^ j;
                if (ixj > i) {
                    unsigned long long a = sk[i], c = sk[ixj];
                    bool desc = ((i & k) == 0);
                    if (desc ? (a < c) : (a > c)) { sk[i] = c; sk[ixj] = a; }
                }
            }
            __syncthreads();
        }
    }

    // decode top PRE boxes (strict non-fused fp32 to track XLA rounding)
    for (int p = tid; p < PRE; p += bs) {
        unsigned long long key = sk[p];
        unsigned idx = 0xFFFFFFFFu - (unsigned)(key & 0xFFFFFFFFull);
        int a = idx % NA;
        int cell = idx / NA;
        int x = cell % FW;
        int y = cell / FW;
        float gy = __fdiv_rn((float)y + 0.5f, (float)FH);
        float gx = __fdiv_rn((float)x + 0.5f, (float)FW);
        float a0 = fminf(fmaxf(__fadd_rn(gy, sbase[a * 4 + 0]), 0.f), 1.f);
        float a1 = fminf(fmaxf(__fadd_rn(gx, sbase[a * 4 + 1]), 0.f), 1.f);
        float a2 = fminf(fmaxf(__fadd_rn(gy, sbase[a * 4 + 2]), 0.f), 1.f);
        float a3 = fminf(fmaxf(__fadd_rn(gx, sbase[a * 4 + 3]), 0.f), 1.f);
        const float* dp =
            deltas + ((((size_t)b * FH + y) * FW + x) * NA + a) * 4;
        float d0 = __fmul_rn(dp[0], 0.1f);
        float d1 = __fmul_rn(dp[1], 0.1f);
        float d2 = __fmul_rn(dp[2], 0.2f);
        float d3 = __fmul_rn(dp[3], 0.2f);
        float ah = __fsub_rn(a2, a0), aw = __fsub_rn(a3, a1);
        float acy = __fadd_rn(a0, __fmul_rn(0.5f, ah));
        float acx = __fadd_rn(a1, __fmul_rn(0.5f, aw));
        float eh = (float)exp((double)d2);   // correctly-rounded fp32 exp
        float ew = (float)exp((double)d3);
        float h = __fmul_rn(eh, ah);
        float w = __fmul_rn(ew, aw);
        float cy = __fadd_rn(__fmul_rn(d0, ah), acy);
        float cx = __fadd_rn(__fmul_rn(d1, aw), acx);
        float4 box;
        box.x = fminf(fmaxf(__fsub_rn(cy, __fmul_rn(0.5f, h)), 0.f), 1.f);
        box.y = fminf(fmaxf(__fsub_rn(cx, __fmul_rn(0.5f, w)), 0.f), 1.f);
        box.z = fminf(fmaxf(__fadd_rn(cy, __fmul_rn(0.5f, h)), 0.f), 1.f);
        box.w = fminf(fmaxf(__fadd_rn(cx, __fmul_rn(0.5f, w)), 0.f), 1.f);
        g_boxes[(size_t)b * PRE + p] = box;
    }
}

// ---------------- suppression decision (identical everywhere) -------------
// suppress <=> __fdiv_rn(inter, denom) > 0.7f; banded multiply gives the
// exact answer outside a +-7e-5 relative band (>> 1ulp of mul/div), rare
// exact fdiv fallback inside the band.
__device__ __forceinline__ bool iou_sup(float4 bi, float ai, float4 bj, float aj) {
    float yy1 = fmaxf(bi.x, bj.x);
    float xx1 = fmaxf(bi.y, bj.y);
    float yy2 = fminf(bi.z, bj.z);
    float xx2 = fminf(bi.w, bj.w);
    float ih = fmaxf(__fsub_rn(yy2, yy1), 0.f);
    float iw = fmaxf(__fsub_rn(xx2, xx1), 0.f);
    float inter = __fmul_rn(ih, iw);
    float denom = __fadd_rn(__fsub_rn(__fadd_rn(ai, aj), inter), 1e-8f);
    if (inter > __fmul_rn(denom, 0.7000500f)) return true;
    if (inter < __fmul_rn(denom, 0.6999500f)) return false;
    return __fdiv_rn(inter, denom) > 0.7f;
}

__device__ __forceinline__ float box_area(float4 v) {
    return __fmul_rn(fmaxf(__fsub_rn(v.z, v.x), 0.f),
                     fmaxf(__fsub_rn(v.w, v.y), 0.f));
}

// ---------------- kernel 5: suppression matrix (full chip) ----------------
// grid (24, 188, BATCH) x 256. Block = 32 rows x 8 words (256 cols).
// Thread (i, w) computes mask word: bit t set iff j=32w+t > i, j < PRE, and
// box_i suppresses box_j. Every existing word is written (no pre-zeroing).
__global__ __launch_bounds__(256) void k_mask() {
    __shared__ float4 rb[32];  __shared__ float ra[32];
    __shared__ float4 cb[256]; __shared__ float ca[256];
    int b = blockIdx.z;
    int r0 = blockIdx.y * 32;
    int w0 = blockIdx.x * 8;
    int c0 = w0 * 32;
    int tid = threadIdx.x;

    int ri = tid >> 3;            // 0..31
    int i = r0 + ri;
    int w = w0 + (tid & 7);

    // tile entirely below the diagonal: all words zero, skip staging
    if (c0 + 255 <= r0) {
        if (i < PRE && w < PREW)
            g_mask[((size_t)b * PRE + i) * PREW + w] = 0u;
        return;
    }

    if (tid < 32) {
        int r = r0 + tid;
        float4 v = (r < PRE) ? g_boxes[(size_t)b * PRE + r]
                             : make_float4(0.f, 0.f, 0.f, 0.f);
        rb[tid] = v; ra[tid] = box_area(v);
    }
    {
        int j = c0 + tid;
        float4 v = (j < PRE) ? g_boxes[(size_t)b * PRE + j]
                             : make_float4(0.f, 0.f, 0.f, 0.f);
        cb[tid] = v; ca[tid] = box_area(v);
    }
    __syncthreads();

    if (i >= PRE || w >= PREW) return;
    unsigned m = 0;
    int jb = w << 5;
    if (jb + 31 > i) {
        float4 bi = rb[ri];
        float ai = ra[ri];
        int lo = jb - c0;
#pragma unroll 8
        for (int t = 0; t < 32; t++) {
            int jj = jb + t;
            if (jj > i && jj < PRE && iou_sup(bi, ai, cb[lo + t], ca[lo + t]))
                m |= 1u << t;
        }
    }
    g_mask[((size_t)b * PRE + i) * PREW + w] = m;
}

// ---------------- kernel 6: bitmap greedy reduce (one block/image) --------
// Walk bits in score order; on each selection OR the selected row into the
// smem removed bitmap (188 coalesced words). Speculative prefetch of the
// likely-next row hides most of the row-load latency.
__global__ __launch_bounds__(256) void k_reduce(float* __restrict__ out) {
    __shared__ unsigned removed[PREW];
    __shared__ int s_sel, s_pf, s_cw;
    int b = blockIdx.x, tid = threadIdx.x;
    if (tid < PREW) removed[tid] = (tid == PREW - 1) ? 0xFFFF0000u : 0u;
    if (tid == 0) s_cw = 0;
    __syncthreads();

    float4* orow = (float4*)(out + (size_t)b * POST * 4);
    int k = 0;
    while (k < POST) {
        if (tid == 0) {
            int cw = s_cw, sel = -1, pf = -1;
            while (cw < PREW) {
                unsigned alive = ~removed[cw];
                if (alive) {
                    int bit = __ffs(alive) - 1;
                    sel = (cw << 5) + bit;
                    removed[cw] |= (1u << bit);
                    // speculative next candidate (pre-OR state)
                    unsigned a2 = ~removed[cw];
                    int cw2 = cw;
                    while (cw2 < PREW && !a2) {
                        cw2++;
                        if (cw2 < PREW) a2 = ~removed[cw2];
                    }
                    if (cw2 < PREW) pf = (cw2 << 5) + (__ffs(a2) - 1);
                    break;
                }
                cw++;
            }
            s_cw = cw; s_sel = sel; s_pf = pf;
        }
        __syncthreads();
        int sel = s_sel;
        if (sel < 0) break;
        const unsigned* row = &g_mask[((size_t)b * PRE + sel) * PREW];
        if (tid < PREW) removed[tid] |= row[tid];
        int pf = s_pf;
        if (pf >= 0 && tid >= 192 && tid < 198) {
            const unsigned* prow =
                &g_mask[((size_t)b * PRE + pf) * PREW] + (tid - 192) * 32;
            asm volatile("prefetch.global.L1 [%0];" :: "l"(prow));
        }
        if (tid == 248) orow[k] = g_boxes[(size_t)b * PRE + sel];
        k++;
        __syncthreads();
    }
    // zero-pad remaining outputs (reference pads with zeros)
    for (int idx = k * 4 + tid; idx < POST * 4; idx += blockDim.x)
        out[(size_t)b * POST * 4 + idx] = 0.0f;
}

// ---------------- launch ---------------------------------------------------
extern "C" void kernel_launch(void* const* d_in, const int* in_sizes, int n_in,
                              void* d_out, int out_size) {
    const float* deltas = (const float*)d_in[0];   // (16,192,192,36)
    const float* scores = (const float*)d_in[1];   // (16,192,192,9)
    const float* banch  = (const float*)d_in[2];   // (9,4)
    float* out = (float*)d_out;                    // (16,1000,4)

    cudaFuncSetAttribute(k_sort_decode,
                         cudaFuncAttributeMaxDynamicSharedMemorySize,
                         CAP * (int)sizeof(unsigned long long));

    dim3 grid2(81, BATCH);                         // exactly 4 float4/thread
    k_hist<<<grid2, 256>>>(scores);
    k_thresh<<<BATCH, 256>>>();
    k_collect<<<grid2, 256>>>(scores);
    k_sort_decode<<<BATCH, 1024, CAP * (int)sizeof(unsigned long long)>>>(
        deltas, banch);
    dim3 gmask(24, 188, BATCH);                    // word-tiles, row-tiles, image
    k_mask<<<gmask, 256>>>();
    k_reduce<<<BATCH, 256>>>(out);
}

// round 13
// speedup vs baseline: 3.4394x; 3.4394x over previous
#include <cuda_runtime.h>
#include <math.h>

#define BATCH 16
#define FH 192
#define FW 192
#define NA 9
#define NPI (FH*FW*NA)      /* 331776 anchors per image */
#define NPI4 (NPI/4)        /* 82944 */
#define PRE 6000
#define POST 1000
#define CAP 8192            /* candidate capacity per image (power of two for bitonic) */
#define HB 65536            /* histogram buckets = top 16 bits of fp32 score */
#define NMSW 128            /* NMS window size (4 mask words) */

// ---------------- device scratch (no allocations allowed) ----------------
__device__ unsigned int       g_hist[BATCH * HB];        // 4 MB (zeroed by k_collect each pass)
__device__ unsigned int       g_cnt[BATCH];
__device__ int                g_thresh[BATCH];
__device__ unsigned long long g_keys[BATCH * CAP];       // 1 MB
__device__ float4             g_boxes[BATCH * PRE];      // 384 KB

// ---------------- kernel 1: score-bit histogram per image -----------------
// grid (81, BATCH) x 256: exactly 4 float4 per thread, batched for MLP.
__global__ void k_hist(const float* __restrict__ scores) {
    int b = blockIdx.y;
    const float4* s4 = (const float4*)(scores + (size_t)b * NPI);
    unsigned* h = g_hist + (size_t)b * HB;
    int i = blockIdx.x * blockDim.x + threadIdx.x;
    int step = gridDim.x * blockDim.x;                  // 20736 = NPI4/4
    float4 v0 = s4[i];
    float4 v1 = s4[i + step];
    float4 v2 = s4[i + 2 * step];
    float4 v3 = s4[i + 3 * step];
    atomicAdd(&h[__float_as_uint(v0.x) >> 16], 1u);
    atomicAdd(&h[__float_as_uint(v0.y) >> 16], 1u);
    atomicAdd(&h[__float_as_uint(v0.z) >> 16], 1u);
    atomicAdd(&h[__float_as_uint(v0.w) >> 16], 1u);
    atomicAdd(&h[__float_as_uint(v1.x) >> 16], 1u);
    atomicAdd(&h[__float_as_uint(v1.y) >> 16], 1u);
    atomicAdd(&h[__float_as_uint(v1.z) >> 16], 1u);
    atomicAdd(&h[__float_as_uint(v1.w) >> 16], 1u);
    atomicAdd(&h[__float_as_uint(v2.x) >> 16], 1u);
    atomicAdd(&h[__float_as_uint(v2.y) >> 16], 1u);
    atomicAdd(&h[__float_as_uint(v2.z) >> 16], 1u);
    atomicAdd(&h[__float_as_uint(v2.w) >> 16], 1u);
    atomicAdd(&h[__float_as_uint(v3.x) >> 16], 1u);
    atomicAdd(&h[__float_as_uint(v3.y) >> 16], 1u);
    atomicAdd(&h[__float_as_uint(v3.z) >> 16], 1u);
    atomicAdd(&h[__float_as_uint(v3.w) >> 16], 1u);
}

// ---------------- kernel 2: per-image threshold bucket --------------------
// Largest bucket T such that count(bucket >= T) >= PRE; resets g_cnt.
__global__ void k_thresh() {
    int b = blockIdx.x;
    int t = threadIdx.x;               // 256 threads, each sums a 256-bucket chunk
    __shared__ unsigned csum[256];
    __shared__ unsigned sbuf[256];
    __shared__ unsigned sfin[256];
    __shared__ int s_chunk;
    __shared__ unsigned s_above;
    const unsigned* h = g_hist + (size_t)b * HB;
    int base = t * 256;
    unsigned s = 0;
    for (int i = 0; i < 256; i++) s += h[base + i];
    csum[t] = s;
    __syncthreads();
    if (t == 0) {
        unsigned cum = 0;
        int c = 255;
        for (; c >= 0; c--) {
            if (cum + csum[c] >= PRE) break;
            cum += csum[c];
        }
        s_chunk = c;
        s_above = cum;                 // count strictly above chunk c
        g_cnt[b] = 0u;                 // reset candidate counter for k_collect
    }
    __syncthreads();
    int c = s_chunk;
    unsigned above = s_above;
    sbuf[t] = h[c * 256 + t];
    __syncthreads();
    // inclusive suffix sum (Hillis-Steele)
    for (int d = 1; d < 256; d <<= 1) {
        unsigned v = (t + d < 256) ? sbuf[t + d] : 0u;
        __syncthreads();
        sbuf[t] += v;
        __syncthreads();
    }
    sfin[t] = sbuf[t];
    __syncthreads();
    // largest index i with suffix(i)+above >= PRE (suffix is non-increasing)
    bool ok = (sfin[t] + above >= PRE);
    bool next_ok = (t < 255) ? (sfin[t + 1] + above >= PRE) : false;
    if (ok && !next_ok) g_thresh[b] = c * 256 + t;
}

// ---------------- kernel 3: collect candidate keys + zero histogram -------
// key = (score_bits << 32) | (~idx): descending sort => score desc, then idx asc
// (matches lax.top_k stable tie-breaking exactly).
__global__ void k_collect(const float* __restrict__ scores) {
    int b = blockIdx.y;
    const float4* s4 = (const float4*)(scores + (size_t)b * NPI);
    int T = g_thresh[b];
    int i = blockIdx.x * blockDim.x + threadIdx.x;
    int step = gridDim.x * blockDim.x;                  // 20736
    float4 v[4];
    v[0] = s4[i]; v[1] = s4[i + step]; v[2] = s4[i + 2 * step];
    v[3] = s4[i + 3 * step];
#pragma unroll
    for (int q = 0; q < 4; q++) {
        unsigned bw[4] = {__float_as_uint(v[q].x), __float_as_uint(v[q].y),
                          __float_as_uint(v[q].z), __float_as_uint(v[q].w)};
#pragma unroll
        for (int c = 0; c < 4; c++) {
            if ((int)(bw[c] >> 16) >= T) {
                unsigned pos = atomicAdd(&g_cnt[b], 1u);
                if (pos < CAP) {
                    unsigned idx = 4u * (unsigned)(i + q * step) + (unsigned)c;
                    g_keys[(size_t)b * CAP + pos] =
                        ((unsigned long long)bw[c] << 32) |
                        (unsigned long long)(0xFFFFFFFFu - idx);
                }
            }
        }
    }
    // zero histogram for next replay
    unsigned* h = g_hist + (size_t)b * HB;
    for (int j = i; j < HB; j += step) h[j] = 0u;
}

// ---------------- kernel 4: per-image bitonic sort + decode ---------------
__global__ __launch_bounds__(1024) void k_sort_decode(
        const float* __restrict__ deltas, const float* __restrict__ banch) {
    extern __shared__ unsigned long long sk[];   // CAP u64 = 64 KB
    __shared__ float sbase[NA * 4];
    int b = blockIdx.x, tid = threadIdx.x, bs = blockDim.x;

    unsigned cnt = g_cnt[b];
    if (cnt > CAP) cnt = CAP;
    for (int i = tid; i < CAP; i += bs)
        sk[i] = ((unsigned)i < cnt) ? g_keys[(size_t)b * CAP + i] : 0ull;
    if (tid < NA * 4) sbase[tid] = banch[tid];
    __syncthreads();

    // bitonic sort, descending
    for (int k = 2; k <= CAP; k <<= 1) {
        for (int j = k >> 1; j > 0; j >>= 1) {
            for (int i = tid; i < CAP; i += bs) {
                int ixj = i ^ j;
                if (ixj > i) {
                    unsigned long long a = sk[i], c = sk[ixj];
                    bool desc = ((i & k) == 0);
                    if (desc ? (a < c) : (a > c)) { sk[i] = c; sk[ixj] = a; }
                }
            }
            __syncthreads();
        }
    }

    // decode top PRE boxes (strict non-fused fp32 to track XLA rounding)
    for (int p = tid; p < PRE; p += bs) {
        unsigned long long key = sk[p];
        unsigned idx = 0xFFFFFFFFu - (unsigned)(key & 0xFFFFFFFFull);
        int a = idx % NA;
        int cell = idx / NA;
        int x = cell % FW;
        int y = cell / FW;
        float gy = __fdiv_rn((float)y + 0.5f, (float)FH);
        float gx = __fdiv_rn((float)x + 0.5f, (float)FW);
        float a0 = fminf(fmaxf(__fadd_rn(gy, sbase[a * 4 + 0]), 0.f), 1.f);
        float a1 = fminf(fmaxf(__fadd_rn(gx, sbase[a * 4 + 1]), 0.f), 1.f);
        float a2 = fminf(fmaxf(__fadd_rn(gy, sbase[a * 4 + 2]), 0.f), 1.f);
        float a3 = fminf(fmaxf(__fadd_rn(gx, sbase[a * 4 + 3]), 0.f), 1.f);
        const float* dp =
            deltas + ((((size_t)b * FH + y) * FW + x) * NA + a) * 4;
        float d0 = __fmul_rn(dp[0], 0.1f);
        float d1 = __fmul_rn(dp[1], 0.1f);
        float d2 = __fmul_rn(dp[2], 0.2f);
        float d3 = __fmul_rn(dp[3], 0.2f);
        float ah = __fsub_rn(a2, a0), aw = __fsub_rn(a3, a1);
        float acy = __fadd_rn(a0, __fmul_rn(0.5f, ah));
        float acx = __fadd_rn(a1, __fmul_rn(0.5f, aw));
        float eh = (float)exp((double)d2);   // correctly-rounded fp32 exp
        float ew = (float)exp((double)d3);
        float h = __fmul_rn(eh, ah);
        float w = __fmul_rn(ew, aw);
        float cy = __fadd_rn(__fmul_rn(d0, ah), acy);
        float cx = __fadd_rn(__fmul_rn(d1, aw), acx);
        float4 box;
        box.x = fminf(fmaxf(__fsub_rn(cy, __fmul_rn(0.5f, h)), 0.f), 1.f);
        box.y = fminf(fmaxf(__fsub_rn(cx, __fmul_rn(0.5f, w)), 0.f), 1.f);
        box.z = fminf(fmaxf(__fadd_rn(cy, __fmul_rn(0.5f, h)), 0.f), 1.f);
        box.w = fminf(fmaxf(__fadd_rn(cx, __fmul_rn(0.5f, w)), 0.f), 1.f);
        g_boxes[(size_t)b * PRE + p] = box;
    }
}

// ---------------- suppression decision (identical everywhere) -------------
// suppress <=> __fdiv_rn(inter, denom) > 0.7f; banded multiply gives the
// exact answer outside a +-7e-5 relative band (>> 1ulp of mul/div), rare
// exact fdiv fallback inside the band.
__device__ __forceinline__ bool iou_sup(float4 bi, float ai, float4 bj, float aj) {
    float yy1 = fmaxf(bi.x, bj.x);
    float xx1 = fmaxf(bi.y, bj.y);
    float yy2 = fminf(bi.z, bj.z);
    float xx2 = fminf(bi.w, bj.w);
    float ih = fmaxf(__fsub_rn(yy2, yy1), 0.f);
    float iw = fmaxf(__fsub_rn(xx2, xx1), 0.f);
    float inter = __fmul_rn(ih, iw);
    float denom = __fadd_rn(__fsub_rn(__fadd_rn(ai, aj), inter), 1e-8f);
    if (inter > __fmul_rn(denom, 0.7000500f)) return true;
    if (inter < __fmul_rn(denom, 0.6999500f)) return false;
    return __fdiv_rn(inter, denom) > 0.7f;
}

__device__ __forceinline__ float box_area(float4 v) {
    return __fmul_rn(fmaxf(__fsub_rn(v.z, v.x), 0.f),
                     fmaxf(__fsub_rn(v.w, v.y), 0.f));
}

// ---------------- kernel 5: lazy-window greedy NMS ------------------------
// Walk the sorted list in 128-candidate windows. Per window:
//   prefilter candidates vs all selections so far (early-exit, bit mask),
//   build the in-window 128x128 suppression matrix (pre-dead rows skipped),
//   warp chain with dead initialized from the prefilter,
//   append selections. Stop at POST picks. No sweep over unselected boxes:
// boxes past the last pick never influence the output.
__global__ __launch_bounds__(512) void k_nms(float* __restrict__ out) {
    __shared__ float4 selb[POST];       // 16 KB selected boxes
    __shared__ float  sela[POST];       //  4 KB selected areas
    __shared__ float4 wb[NMSW];
    __shared__ float  wa[NMSW];
    __shared__ unsigned sup[NMSW * 4];  // in-window suppression matrix
    __shared__ unsigned pdm[4];         // pre-dead bit mask (from prefilter)
    __shared__ unsigned short spos[NMSW];
    __shared__ int s_nsel;

    int b = blockIdx.x, tid = threadIdx.x;
    float4* orow4 = (float4*)(out + (size_t)b * POST * 4);

    int k = 0, pos = 0;
    while (k < POST && pos < PRE) {
        int w = PRE - pos; if (w > NMSW) w = NMSW;

        // ---- stage window ----
        if (tid < 4) pdm[tid] = 0u;
        if (tid < w) {
            float4 v = g_boxes[(size_t)b * PRE + pos + tid];
            wb[tid] = v;
            wa[tid] = box_area(v);
        }
        __syncthreads();

        // ---- prefilter: 4 threads per candidate vs selections (early exit)
        if (tid < w * 4) {
            int j = tid >> 2, sub = tid & 3;
            float4 bj = wb[j];
            float aj = wa[j];
            for (int s = sub; s < k; s += 4) {
                if (iou_sup(selb[s], sela[s], bj, aj)) {
                    atomicOr(&pdm[j >> 5], 1u << (j & 31));
                    break;
                }
            }
        }
        __syncthreads();

        // ---- in-window matrix: 128 rows x 4 words (512 units) ----
        {
            int p = tid >> 2, wd = tid & 3;
            unsigned m = 0;
            int jb = wd << 5;
            bool prow_dead = (pdm[p >> 5] >> (p & 31)) & 1u;
            if (p < w && jb + 31 > p && !prow_dead) {
                float4 bp = wb[p];
                float ap = wa[p];
#pragma unroll 8
                for (int t = 0; t < 32; t++) {
                    int q = jb + t;
                    if (q > p && q < w && iou_sup(bp, ap, wb[q], wa[q]))
                        m |= 1u << t;
                }
            }
            sup[tid] = m;
        }
        __syncthreads();

        // ---- warp-parallel greedy chain, dead init = prefilter mask ----
        if (tid < 32) {
            int lane = tid;
            unsigned valid = 0;
            if (lane < 4) {
                int hi = w - (lane << 5);
                valid = (hi >= 32) ? 0xffffffffu
                                   : (hi > 0 ? ((1u << hi) - 1u) : 0u);
            }
            unsigned dead = (lane < 4) ? pdm[lane] : 0u;
            int nsel = 0;
            int lim = POST - k; if (lim > w) lim = w;
            for (;;) {
                unsigned alive = ~dead & valid;
                unsigned cand = alive ? (((unsigned)lane << 5) |
                                         (unsigned)(__ffs(alive) - 1))
                                      : 0xffffffffu;
                unsigned p = __reduce_min_sync(0xffffffffu, cand);
                if (p == 0xffffffffu) break;
                if (lane == 0) spos[nsel] = (unsigned short)p;
                nsel++;
                if (nsel >= lim) break;
                if (lane < 4) dead |= sup[((int)p << 2) + lane];
                if ((p >> 5) == (unsigned)lane) dead |= 1u << (p & 31);
            }
            if (lane == 0) s_nsel = nsel;
        }
        __syncthreads();
        int nsel = s_nsel;

        // ---- append selections, write outputs ----
        if (tid < nsel) {
            int p = spos[tid];
            float4 v = wb[p];
            selb[k + tid] = v;
            sela[k + tid] = wa[p];
            orow4[k + tid] = v;
        }
        k += nsel;
        pos += w;
        __syncthreads();
    }
    // zero-pad remaining outputs (reference pads with zeros)
    for (int idx = k * 4 + tid; idx < POST * 4; idx += blockDim.x)
        out[(size_t)b * POST * 4 + idx] = 0.0f;
}

// ---------------- launch ---------------------------------------------------
extern "C" void kernel_launch(void* const* d_in, const int* in_sizes, int n_in,
                              void* d_out, int out_size) {
    const float* deltas = (const float*)d_in[0];   // (16,192,192,36)
    const float* scores = (const float*)d_in[1];   // (16,192,192,9)
    const float* banch  = (const float*)d_in[2];   // (9,4)
    float* out = (float*)d_out;                    // (16,1000,4)

    cudaFuncSetAttribute(k_sort_decode,
                         cudaFuncAttributeMaxDynamicSharedMemorySize,
                         CAP * (int)sizeof(unsigned long long));

    dim3 grid2(81, BATCH);                         // exactly 4 float4/thread
    k_hist<<<grid2, 256>>>(scores);
    k_thresh<<<BATCH, 256>>>();
    k_collect<<<grid2, 256>>>(scores);
    k_sort_decode<<<BATCH, 1024, CAP * (int)sizeof(unsigned long long)>>>(
        deltas, banch);
    k_nms<<<BATCH, 512>>>(out);
}

// round 14
// speedup vs baseline: 3.9592x; 1.1511x over previous
#include <cuda_runtime.h>
#include <math.h>

#define BATCH 16
#define FH 192
#define FW 192
#define NA 9
#define NPI (FH*FW*NA)      /* 331776 anchors per image */
#define NPI4 (NPI/4)        /* 82944 */
#define PRE 6000
#define POST 1000
#define CAP 8192            /* candidate capacity per image (power of two for bitonic) */
#define HB 65536            /* histogram buckets = top 16 bits of fp32 score */
#define NMSW 128            /* NMS window size (4 mask words) */

// ---------------- device scratch (no allocations allowed) ----------------
__device__ unsigned int       g_hist[BATCH * HB];        // 4 MB (zeroed by k_collect each pass)
__device__ unsigned int       g_cnt[BATCH];
__device__ int                g_thresh[BATCH];
__device__ unsigned long long g_keys[BATCH * CAP];       // 1 MB
__device__ float4             g_boxes[BATCH * PRE];      // 384 KB

// ---------------- kernel 1: score-bit histogram per image -----------------
// grid (81, BATCH) x 256: exactly 4 float4 per thread, batched for MLP.
__global__ void k_hist(const float* __restrict__ scores) {
    int b = blockIdx.y;
    const float4* s4 = (const float4*)(scores + (size_t)b * NPI);
    unsigned* h = g_hist + (size_t)b * HB;
    int i = blockIdx.x * blockDim.x + threadIdx.x;
    int step = gridDim.x * blockDim.x;                  // 20736 = NPI4/4
    float4 v0 = s4[i];
    float4 v1 = s4[i + step];
    float4 v2 = s4[i + 2 * step];
    float4 v3 = s4[i + 3 * step];
    atomicAdd(&h[__float_as_uint(v0.x) >> 16], 1u);
    atomicAdd(&h[__float_as_uint(v0.y) >> 16], 1u);
    atomicAdd(&h[__float_as_uint(v0.z) >> 16], 1u);
    atomicAdd(&h[__float_as_uint(v0.w) >> 16], 1u);
    atomicAdd(&h[__float_as_uint(v1.x) >> 16], 1u);
    atomicAdd(&h[__float_as_uint(v1.y) >> 16], 1u);
    atomicAdd(&h[__float_as_uint(v1.z) >> 16], 1u);
    atomicAdd(&h[__float_as_uint(v1.w) >> 16], 1u);
    atomicAdd(&h[__float_as_uint(v2.x) >> 16], 1u);
    atomicAdd(&h[__float_as_uint(v2.y) >> 16], 1u);
    atomicAdd(&h[__float_as_uint(v2.z) >> 16], 1u);
    atomicAdd(&h[__float_as_uint(v2.w) >> 16], 1u);
    atomicAdd(&h[__float_as_uint(v3.x) >> 16], 1u);
    atomicAdd(&h[__float_as_uint(v3.y) >> 16], 1u);
    atomicAdd(&h[__float_as_uint(v3.z) >> 16], 1u);
    atomicAdd(&h[__float_as_uint(v3.w) >> 16], 1u);
}

// ---------------- kernel 2: per-image threshold bucket --------------------
// Largest bucket T such that count(bucket >= T) >= PRE; resets g_cnt.
__global__ void k_thresh() {
    int b = blockIdx.x;
    int t = threadIdx.x;               // 256 threads, each sums a 256-bucket chunk
    __shared__ unsigned csum[256];
    __shared__ unsigned sbuf[256];
    __shared__ unsigned sfin[256];
    __shared__ int s_chunk;
    __shared__ unsigned s_above;
    const unsigned* h = g_hist + (size_t)b * HB;
    int base = t * 256;
    unsigned s = 0;
    for (int i = 0; i < 256; i++) s += h[base + i];
    csum[t] = s;
    __syncthreads();
    if (t == 0) {
        unsigned cum = 0;
        int c = 255;
        for (; c >= 0; c--) {
            if (cum + csum[c] >= PRE) break;
            cum += csum[c];
        }
        s_chunk = c;
        s_above = cum;                 // count strictly above chunk c
        g_cnt[b] = 0u;                 // reset candidate counter for k_collect
    }
    __syncthreads();
    int c = s_chunk;
    unsigned above = s_above;
    sbuf[t] = h[c * 256 + t];
    __syncthreads();
    // inclusive suffix sum (Hillis-Steele)
    for (int d = 1; d < 256; d <<= 1) {
        unsigned v = (t + d < 256) ? sbuf[t + d] : 0u;
        __syncthreads();
        sbuf[t] += v;
        __syncthreads();
    }
    sfin[t] = sbuf[t];
    __syncthreads();
    // largest index i with suffix(i)+above >= PRE (suffix is non-increasing)
    bool ok = (sfin[t] + above >= PRE);
    bool next_ok = (t < 255) ? (sfin[t + 1] + above >= PRE) : false;
    if (ok && !next_ok) g_thresh[b] = c * 256 + t;
}

// ---------------- kernel 3: collect candidate keys + zero histogram -------
// key = (score_bits << 32) | (~idx): descending sort => score desc, then idx asc
// (matches lax.top_k stable tie-breaking exactly).
__global__ void k_collect(const float* __restrict__ scores) {
    int b = blockIdx.y;
    const float4* s4 = (const float4*)(scores + (size_t)b * NPI);
    int T = g_thresh[b];
    int i = blockIdx.x * blockDim.x + threadIdx.x;
    int step = gridDim.x * blockDim.x;                  // 20736
    float4 v[4];
    v[0] = s4[i]; v[1] = s4[i + step]; v[2] = s4[i + 2 * step];
    v[3] = s4[i + 3 * step];
#pragma unroll
    for (int q = 0; q < 4; q++) {
        unsigned bw[4] = {__float_as_uint(v[q].x), __float_as_uint(v[q].y),
                          __float_as_uint(v[q].z), __float_as_uint(v[q].w)};
#pragma unroll
        for (int c = 0; c < 4; c++) {
            if ((int)(bw[c] >> 16) >= T) {
                unsigned pos = atomicAdd(&g_cnt[b], 1u);
                if (pos < CAP) {
                    unsigned idx = 4u * (unsigned)(i + q * step) + (unsigned)c;
                    g_keys[(size_t)b * CAP + pos] =
                        ((unsigned long long)bw[c] << 32) |
                        (unsigned long long)(0xFFFFFFFFu - idx);
                }
            }
        }
    }
    // zero histogram for next replay
    unsigned* h = g_hist + (size_t)b * HB;
    for (int j = i; j < HB; j += step) h[j] = 0u;
}

// ---------------- kernel 4: per-image bitonic sort + decode ---------------
// Register-blocked: each thread owns 8 consecutive elements; all j<=4
// passes run in registers (direction per element; base is 8-aligned so
// (base+idx)&k2 is exact). Smem passes only for j>=8.
__global__ __launch_bounds__(1024) void k_sort_decode(
        const float* __restrict__ deltas, const float* __restrict__ banch) {
    extern __shared__ unsigned long long sk[];   // CAP u64 = 64 KB
    __shared__ float sbase[NA * 4];
    int b = blockIdx.x, tid = threadIdx.x, bs = blockDim.x;

    unsigned cnt = g_cnt[b];
    if (cnt > CAP) cnt = CAP;
    for (int i = tid; i < CAP; i += bs)
        sk[i] = ((unsigned)i < cnt) ? g_keys[(size_t)b * CAP + i] : 0ull;
    if (tid < NA * 4) sbase[tid] = banch[tid];
    __syncthreads();

    // bitonic sort, descending
    for (int k2 = 2; k2 <= CAP; k2 <<= 1) {
        for (int j = k2 >> 1; j >= 8; j >>= 1) {
            for (int i = tid; i < CAP; i += bs) {
                int ixj = i ^ j;
                if (ixj > i) {
                    unsigned long long a = sk[i], c = sk[ixj];
                    bool desc = ((i & k2) == 0);
                    if (desc ? (a < c) : (a > c)) { sk[i] = c; sk[ixj] = a; }
                }
            }
            __syncthreads();
        }
        // fused register pass: j = 4, 2, 1 (those with j < k2)
        {
            int base = tid * 8;                  // bs*8 == CAP exactly
            unsigned long long v[8];
#pragma unroll
            for (int q = 0; q < 8; q++) v[q] = sk[base + q];
#pragma unroll
            for (int j = 4; j >= 1; j >>= 1) {
                if (j < k2) {
#pragma unroll
                    for (int idx = 0; idx < 8; idx++) {
                        if ((idx & j) == 0) {
                            int ix2 = idx | j;
                            bool desc = (((base + idx) & k2) == 0);
                            unsigned long long a = v[idx], c = v[ix2];
                            if (desc ? (a < c) : (a > c)) { v[idx] = c; v[ix2] = a; }
                        }
                    }
                }
            }
#pragma unroll
            for (int q = 0; q < 8; q++) sk[base + q] = v[q];
            __syncthreads();
        }
    }

    // decode top PRE boxes (strict non-fused fp32 to track XLA rounding)
    for (int p = tid; p < PRE; p += bs) {
        unsigned long long key = sk[p];
        unsigned idx = 0xFFFFFFFFu - (unsigned)(key & 0xFFFFFFFFull);
        int a = idx % NA;
        int cell = idx / NA;
        int x = cell % FW;
        int y = cell / FW;
        float gy = __fdiv_rn((float)y + 0.5f, (float)FH);
        float gx = __fdiv_rn((float)x + 0.5f, (float)FW);
        float a0 = fminf(fmaxf(__fadd_rn(gy, sbase[a * 4 + 0]), 0.f), 1.f);
        float a1 = fminf(fmaxf(__fadd_rn(gx, sbase[a * 4 + 1]), 0.f), 1.f);
        float a2 = fminf(fmaxf(__fadd_rn(gy, sbase[a * 4 + 2]), 0.f), 1.f);
        float a3 = fminf(fmaxf(__fadd_rn(gx, sbase[a * 4 + 3]), 0.f), 1.f);
        const float* dp =
            deltas + ((((size_t)b * FH + y) * FW + x) * NA + a) * 4;
        float d0 = __fmul_rn(dp[0], 0.1f);
        float d1 = __fmul_rn(dp[1], 0.1f);
        float d2 = __fmul_rn(dp[2], 0.2f);
        float d3 = __fmul_rn(dp[3], 0.2f);
        float ah = __fsub_rn(a2, a0), aw = __fsub_rn(a3, a1);
        float acy = __fadd_rn(a0, __fmul_rn(0.5f, ah));
        float acx = __fadd_rn(a1, __fmul_rn(0.5f, aw));
        float eh = (float)exp((double)d2);   // correctly-rounded fp32 exp
        float ew = (float)exp((double)d3);
        float h = __fmul_rn(eh, ah);
        float w = __fmul_rn(ew, aw);
        float cy = __fadd_rn(__fmul_rn(d0, ah), acy);
        float cx = __fadd_rn(__fmul_rn(d1, aw), acx);
        float4 box;
        box.x = fminf(fmaxf(__fsub_rn(cy, __fmul_rn(0.5f, h)), 0.f), 1.f);
        box.y = fminf(fmaxf(__fsub_rn(cx, __fmul_rn(0.5f, w)), 0.f), 1.f);
        box.z = fminf(fmaxf(__fadd_rn(cy, __fmul_rn(0.5f, h)), 0.f), 1.f);
        box.w = fminf(fmaxf(__fadd_rn(cx, __fmul_rn(0.5f, w)), 0.f), 1.f);
        g_boxes[(size_t)b * PRE + p] = box;
    }
}

// ---------------- suppression decision (identical everywhere) -------------
// suppress <=> __fdiv_rn(inter, denom) > 0.7f; banded multiply gives the
// exact answer outside a +-7e-5 relative band (>> 1ulp of mul/div), rare
// exact fdiv fallback inside the band.
__device__ __forceinline__ bool iou_sup(float4 bi, float ai, float4 bj, float aj) {
    float yy1 = fmaxf(bi.x, bj.x);
    float xx1 = fmaxf(bi.y, bj.y);
    float yy2 = fminf(bi.z, bj.z);
    float xx2 = fminf(bi.w, bj.w);
    float ih = fmaxf(__fsub_rn(yy2, yy1), 0.f);
    float iw = fmaxf(__fsub_rn(xx2, xx1), 0.f);
    float inter = __fmul_rn(ih, iw);
    float denom = __fadd_rn(__fsub_rn(__fadd_rn(ai, aj), inter), 1e-8f);
    if (inter > __fmul_rn(denom, 0.7000500f)) return true;
    if (inter < __fmul_rn(denom, 0.6999500f)) return false;
    return __fdiv_rn(inter, denom) > 0.7f;
}

__device__ __forceinline__ float box_area(float4 v) {
    return __fmul_rn(fmaxf(__fsub_rn(v.z, v.x), 0.f),
                     fmaxf(__fsub_rn(v.w, v.y), 0.f));
}

// ---------------- kernel 5: lazy-window NMS with overlapped prefilter -----
// Per window n: build in-window matrix; then CONCURRENTLY warp 0 runs the
// greedy chain (single-lane, register dead mask) while warps 1-31 stage
// window n+1 and prefilter it against all selections known so far; after
// the chain, only the freshly-selected ~nsel boxes remain to test.
__global__ __launch_bounds__(1024) void k_nms(float* __restrict__ out) {
    __shared__ float4 selb[POST];        // selected boxes (prefilter source)
    __shared__ float  sela[POST];
    __shared__ float4 wb[2][NMSW];
    __shared__ float  wa[2][NMSW];
    __shared__ uint4  sup4[NMSW];        // in-window matrix, 16B rows
    __shared__ unsigned pdm[2][4];       // pre-dead masks
    __shared__ unsigned short spos[NMSW];
    __shared__ int s_nsel;
    unsigned* sup = (unsigned*)sup4;

    int b = blockIdx.x, tid = threadIdx.x;
    float4* orow4 = (float4*)(out + (size_t)b * POST * 4);

    // initial stage of window 0
    if (tid < NMSW) {
        float4 v = g_boxes[(size_t)b * PRE + tid];
        wb[0][tid] = v;
        wa[0][tid] = box_area(v);
    }
    if (tid >= 1016) pdm[(tid - 1016) >> 2][tid & 3] = 0u;
    __syncthreads();

    int k = 0, pos = 0, cur = 0;
    while (k < POST && pos < PRE) {
        int w = PRE - pos; if (w > NMSW) w = NMSW;
        int nxt = cur ^ 1;
        int npos = pos + w;
        int wn = PRE - npos; if (wn > NMSW) wn = NMSW;   // may be <= 0

        // ---- matrix phase (tid<512) + zero pdm[nxt] (tail threads) ----
        if (tid < 512) {
            int p = tid >> 2, wd = tid & 3;
            unsigned m = 0;
            int jb = wd << 5;
            bool prow_dead = (pdm[cur][p >> 5] >> (p & 31)) & 1u;
            if (p < w && jb + 31 > p && !prow_dead) {
                float4 bp = wb[cur][p];
                float ap = wa[cur][p];
#pragma unroll 8
                for (int t = 0; t < 32; t++) {
                    int q = jb + t;
                    if (q > p && q < w && iou_sup(bp, ap, wb[cur][q], wa[cur][q]))
                        m |= 1u << t;
                }
            }
            sup[tid] = m;
        } else if (tid >= 1020) {
            pdm[nxt][tid - 1020] = 0u;
        }
        __syncthreads();

        // ---- parallel phase ----
        if (tid < 32) {
            // warp 0: single-lane register chain
            if (tid == 0) {
                unsigned dead[4];
#pragma unroll
                for (int wd = 0; wd < 4; wd++) {
                    int hi = w - (wd << 5);
                    unsigned valid = (hi >= 32) ? 0xffffffffu
                                                : (hi > 0 ? ((1u << hi) - 1u) : 0u);
                    dead[wd] = pdm[cur][wd] | ~valid;
                }
                int nsel = 0;
                int lim = POST - k; if (lim > w) lim = w;
                while (nsel < lim) {
                    int p = -1;
#pragma unroll
                    for (int wd = 0; wd < 4; wd++) {
                        unsigned a = ~dead[wd];
                        if (p < 0 && a) p = (wd << 5) + __ffs(a) - 1;
                    }
                    if (p < 0) break;
                    spos[nsel++] = (unsigned short)p;
                    dead[p >> 5] |= 1u << (p & 31);
                    if (nsel >= lim) break;
                    uint4 r = sup4[p];
                    dead[0] |= r.x; dead[1] |= r.y;
                    dead[2] |= r.z; dead[3] |= r.w;
                }
                s_nsel = nsel;
            }
        } else {
            // warps 1-31: stage next window, then prefilter vs known sels
            if (wn > 0) {
                int t2 = tid - 32;
                if (t2 < wn) {
                    float4 v = g_boxes[(size_t)b * PRE + npos + t2];
                    wb[nxt][t2] = v;
                    wa[nxt][t2] = box_area(v);
                }
            }
            asm volatile("bar.sync 1, 992;" ::: "memory");
            if (wn > 0 && k > 0) {
                int worker = tid - 32;               // 0..991; use 896 = 128*7
                if (worker < 896) {
                    int j = worker & 127, sub = worker >> 7;   // sub 0..6
                    if (j < wn) {
                        float4 bj = wb[nxt][j];
                        float aj = wa[nxt][j];
                        for (int s = sub; s < k; s += 7) {
                            if (iou_sup(selb[s], sela[s], bj, aj)) {
                                atomicOr(&pdm[nxt][j >> 5], 1u << (j & 31));
                                break;
                            }
                        }
                    }
                }
            }
        }
        __syncthreads();
        int nsel = s_nsel;

        // ---- append selections + incremental prefilter vs new sels ----
        if (tid < nsel) {
            int p = spos[tid];
            float4 v = wb[cur][p];
            selb[k + tid] = v;
            sela[k + tid] = wa[cur][p];
            orow4[k + tid] = v;
        }
        if (wn > 0 && nsel > 0) {
            int j = tid & 127, sub = tid >> 7;       // 8 threads per candidate
            if (j < wn && !((pdm[nxt][j >> 5] >> (j & 31)) & 1u)) {
                float4 bj = wb[nxt][j];
                float aj = wa[nxt][j];
                for (int s = sub; s < nsel; s += 8) {
                    int ps = spos[s];
                    if (iou_sup(wb[cur][ps], wa[cur][ps], bj, aj)) {
                        atomicOr(&pdm[nxt][j >> 5], 1u << (j & 31));
                        break;
                    }
                }
            }
        }
        k += nsel;
        pos = npos;
        cur = nxt;
        __syncthreads();
    }
    // zero-pad remaining outputs (reference pads with zeros)
    for (int idx = k * 4 + tid; idx < POST * 4; idx += blockDim.x)
        out[(size_t)b * POST * 4 + idx] = 0.0f;
}

// ---------------- launch ---------------------------------------------------
extern "C" void kernel_launch(void* const* d_in, const int* in_sizes, int n_in,
                              void* d_out, int out_size) {
    const float* deltas = (const float*)d_in[0];   // (16,192,192,36)
    const float* scores = (const float*)d_in[1];   // (16,192,192,9)
    const float* banch  = (const float*)d_in[2];   // (9,4)
    float* out = (float*)d_out;                    // (16,1000,4)

    cudaFuncSetAttribute(k_sort_decode,
                         cudaFuncAttributeMaxDynamicSharedMemorySize,
                         CAP * (int)sizeof(unsigned long long));

    dim3 grid2(81, BATCH);                         // exactly 4 float4/thread
    k_hist<<<grid2, 256>>>(scores);
    k_thresh<<<BATCH, 256>>>();
    k_collect<<<grid2, 256>>>(scores);
    k_sort_decode<<<BATCH, 1024, CAP * (int)sizeof(unsigned long long)>>>(
        deltas, banch);
    k_nms<<<BATCH, 1024>>>(out);
}